// round 4
// baseline (speedup 1.0000x reference)
#include <cuda_runtime.h>

#define B_   32
#define T_   256
#define F_   64
#define C_   16
#define CO_  16
#define P_   64
#define S_   32
#define K_   4
#define FC   1024
#define KIN  1056
#define OUTC 96
#define ROWS (B_*T_)        // 8192
#define TT   32             // rows (t) per block
#define NBLK (ROWS/TT)      // 256 blocks
#define ROWSTRIDE (F_*OUTC) // 6144 floats per (b,t) row

// ---------------- packed f32x2 helpers ----------------
__device__ __forceinline__ double pack2(float lo, float hi) {
    double d; asm("mov.b64 %0, {%1, %2};" : "=d"(d) : "f"(lo), "f"(hi)); return d;
}
__device__ __forceinline__ float2 unpack2(double d) {
    float2 v; asm("mov.b64 {%0, %1}, %2;" : "=f"(v.x), "=f"(v.y) : "d"(d)); return v;
}
__device__ __forceinline__ void fma2(double& acc, double a, double b) {
    asm("fma.rn.f32x2 %0, %1, %2, %3;" : "=d"(acc) : "d"(a), "d"(b), "d"(acc));
}

struct SmemGemm {                              // 20.8 KB
    alignas(16) float AsT[32][34];             // k-major A tile, m-pairs LDS.64-able
    alignas(16) float Bsdup[32][128];          // B tile,每 value duplicated (LDS.128 -> 2 packed b)
};
struct SmemConv {                              // ~64 KB
    alignas(16) double xsl_d[4][38][19];       // x slab as (a,a) dup doubles, pad 19 (conflict-free)
    alignas(16) float  xsl  [4][38][20];       // plain x slab for passthrough (float4-aligned)
    alignas(16) float  ws   [4][64][18];       // weights [f'][c*4+k][co], even pad for LDS.64
    alignas(16) float  stg  [4][TT][20];       // relu(conv+bias) staging
    alignas(16) float  bs   [4][16];
};
union SmemU { SmemGemm g; SmemConv c; };

__global__ __launch_bounds__(256, 2)
void tpc_one(const float* __restrict__ x,
             const float* __restrict__ stat,
             const float* __restrict__ conv_w,
             const float* __restrict__ conv_b,
             const float* __restrict__ W_p,
             const float* __restrict__ b_p,
             float* __restrict__ out)
{
    __shared__ alignas(16) float gp[TT][68];   // relu(point_out) tile, 8.7 KB
    __shared__ SmemU sm;

    const int tid  = threadIdx.x;
    const int row0 = blockIdx.x * TT;          // 32 rows, all within one b
    const int b    = row0 >> 8;
    const bool at_seq_start = ((row0 & 255) == 0);

    // ===================== PHASE A: point GEMM -> gp =====================
    {
        const int mp = tid >> 4;               // 0..15 (m-pair)
        const int ng = tid & 15;               // 0..15 (4 n each)
        const int m0 = mp * 2;
        const int n0 = ng * 4;

        double acc[4] = {0.0, 0.0, 0.0, 0.0};

        const int lr = tid >> 3;               // A-load row 0..31
        const int lk = tid & 7;                // A-load k-quad 0..7

        for (int kb = 0; kb < 33; ++kb) {      // 33 * 32 = 1056
            const int kg0 = kb * 32;
            // A tile: one float4 per thread
            {
                int kgf = kg0 + lk * 4;
                float4 v;
                if (kgf < FC)
                    v = *reinterpret_cast<const float4*>(&x[(size_t)(row0 + lr) * FC + kgf]);
                else
                    v = *reinterpret_cast<const float4*>(&stat[b * S_ + (kgf - FC)]);
                sm.g.AsT[lk * 4 + 0][lr] = v.x;
                sm.g.AsT[lk * 4 + 1][lr] = v.y;
                sm.g.AsT[lk * 4 + 2][lr] = v.z;
                sm.g.AsT[lk * 4 + 3][lr] = v.w;
            }
            // B tile duplicated: 512 source float4, 2 per thread
            #pragma unroll
            for (int l = 0; l < 2; ++l) {
                int idx = tid + l * 256;
                int kk  = idx >> 4;
                int nq  = idx & 15;
                float4 v = *reinterpret_cast<const float4*>(&W_p[(size_t)(kg0 + kk) * P_ + nq * 4]);
                float4 d0 = make_float4(v.x, v.x, v.y, v.y);
                float4 d1 = make_float4(v.z, v.z, v.w, v.w);
                *reinterpret_cast<float4*>(&sm.g.Bsdup[kk][nq * 8])     = d0;
                *reinterpret_cast<float4*>(&sm.g.Bsdup[kk][nq * 8 + 4]) = d1;
            }
            __syncthreads();

            #pragma unroll
            for (int kk = 0; kk < 32; ++kk) {
                double a    = *reinterpret_cast<const double*>(&sm.g.AsT[kk][m0]);
                double2 b01 = *reinterpret_cast<const double2*>(&sm.g.Bsdup[kk][ng * 8]);
                double2 b23 = *reinterpret_cast<const double2*>(&sm.g.Bsdup[kk][ng * 8 + 4]);
                fma2(acc[0], a, b01.x);
                fma2(acc[1], a, b01.y);
                fma2(acc[2], a, b23.x);
                fma2(acc[3], a, b23.y);
            }
            __syncthreads();
        }

        // epilogue: bias + relu -> gp
        float4 bb = *reinterpret_cast<const float4*>(&b_p[n0]);
        float bbv[4] = {bb.x, bb.y, bb.z, bb.w};
        #pragma unroll
        for (int j = 0; j < 4; ++j) {
            float2 p = unpack2(acc[j]);
            gp[m0][n0 + j]     = fmaxf(p.x + bbv[j], 0.f);
            gp[m0 + 1][n0 + j] = fmaxf(p.y + bbv[j], 0.f);
        }
    }
    __syncthreads();

    // ===================== PHASE B: conv + output assembly =====================
    const int fp  = tid >> 6;                  // f' 0..3
    const int tg  = (tid >> 3) & 7;            // t-group (4 t each)
    const int cg  = tid & 7;                   // co-pair group
    const int t0  = tg * 4;
    const int co0 = cg * 2;

    for (int fc = 0; fc < 16; ++fc) {
        const int fbase = fc * 4;
        __syncthreads();                       // guard reuse of smem from prev iter

        // ---- load x slabs (plain + dup-double), 608 float4 sources ----
        #pragma unroll
        for (int l = 0; l < 3; ++l) {
            int idx = tid + l * 256;
            if (idx < 608) {
                int fq  = idx / 152;
                int rem = idx - fq * 152;
                int r   = rem >> 2;            // 0..37 (t = row0 + r - 6)
                int q   = rem & 3;
                float4 v;
                if (at_seq_start && r < 6) v = make_float4(0.f, 0.f, 0.f, 0.f);
                else
                    v = *reinterpret_cast<const float4*>(
                        &x[((size_t)(row0 + r - 6) * F_ + (fbase + fq)) * C_ + q * 4]);
                *reinterpret_cast<float4*>(&sm.c.xsl[fq][r][q * 4]) = v;
                sm.c.xsl_d[fq][r][q * 4 + 0] = pack2(v.x, v.x);
                sm.c.xsl_d[fq][r][q * 4 + 1] = pack2(v.y, v.y);
                sm.c.xsl_d[fq][r][q * 4 + 2] = pack2(v.z, v.z);
                sm.c.xsl_d[fq][r][q * 4 + 3] = pack2(v.w, v.w);
            }
        }
        // ---- load weights: 1024 float4, transposed to [ck][co] ----
        #pragma unroll
        for (int l = 0; l < 4; ++l) {
            int idx = tid + l * 256;
            int fq  = idx >> 8;
            int rem = idx & 255;
            int co  = rem >> 4;
            int c   = rem & 15;
            float4 w = *reinterpret_cast<const float4*>(
                &conv_w[((size_t)(fbase + fq) * CO_ + co) * 64 + c * 4]);
            sm.c.ws[fq][c * 4 + 0][co] = w.x;
            sm.c.ws[fq][c * 4 + 1][co] = w.y;
            sm.c.ws[fq][c * 4 + 2][co] = w.z;
            sm.c.ws[fq][c * 4 + 3][co] = w.w;
        }
        if (tid < 64) sm.c.bs[tid >> 4][tid & 15] = conv_b[(fbase + (tid >> 4)) * CO_ + (tid & 15)];
        __syncthreads();

        // ---- conv compute: 4 t x 2 co per thread ----
        double acc4[4] = {0.0, 0.0, 0.0, 0.0};
        #pragma unroll
        for (int c = 0; c < C_; ++c) {
            double ad[10];
            #pragma unroll
            for (int r = 0; r < 10; ++r) ad[r] = sm.c.xsl_d[fp][t0 + r][c];
            #pragma unroll
            for (int k = 0; k < K_; ++k) {
                double w = *reinterpret_cast<const double*>(&sm.c.ws[fp][c * 4 + k][co0]);
                fma2(acc4[0], ad[0 + 2 * k], w);
                fma2(acc4[1], ad[1 + 2 * k], w);
                fma2(acc4[2], ad[2 + 2 * k], w);
                fma2(acc4[3], ad[3 + 2 * k], w);
            }
        }
        // bias + relu -> staging
        {
            float bx = sm.c.bs[fp][co0];
            float by = sm.c.bs[fp][co0 + 1];
            #pragma unroll
            for (int i = 0; i < 4; ++i) {
                float2 p = unpack2(acc4[i]);
                float2 r2 = make_float2(fmaxf(p.x + bx, 0.f), fmaxf(p.y + by, 0.f));
                *reinterpret_cast<float2*>(&sm.c.stg[fp][t0 + i][co0]) = r2;
            }
        }
        __syncthreads();

        // ---- stores: full coalesced lines ----
        // line 0 (ch 0..31): 1024 float4
        #pragma unroll
        for (int l = 0; l < 4; ++l) {
            int flat = tid + l * 256;
            int q  = flat & 7;
            int fq = (flat >> 3) & 3;
            int t  = flat >> 5;
            float4 v;
            if (q < 4) {
                v = *reinterpret_cast<const float4*>(&sm.c.xsl[fq][t + 6][q * 4]);
                v.x = fmaxf(v.x, 0.f); v.y = fmaxf(v.y, 0.f);
                v.z = fmaxf(v.z, 0.f); v.w = fmaxf(v.w, 0.f);
            } else {
                v = *reinterpret_cast<const float4*>(&sm.c.stg[fq][t][(q - 4) * 4]);
            }
            *reinterpret_cast<float4*>(
                &out[(size_t)(row0 + t) * ROWSTRIDE + (fbase + fq) * OUTC + q * 4]) = v;
        }
        // ch 32..95: 2048 float4 from gp
        #pragma unroll
        for (int l = 0; l < 8; ++l) {
            int flat = tid + l * 256;
            int q  = flat & 15;
            int fq = (flat >> 4) & 3;
            int t  = flat >> 6;
            float4 v = *reinterpret_cast<const float4*>(&gp[t][q * 4]);
            *reinterpret_cast<float4*>(
                &out[(size_t)(row0 + t) * ROWSTRIDE + (fbase + fq) * OUTC + 32 + q * 4]) = v;
        }
    }
}

extern "C" void kernel_launch(void* const* d_in, const int* in_sizes, int n_in,
                              void* d_out, int out_size)
{
    const float* x      = (const float*)d_in[0];   // [32,256,64,16]
    const float* statv  = (const float*)d_in[1];   // [32,32]
    const float* conv_w = (const float*)d_in[2];   // [64,16,16,4]
    const float* conv_b = (const float*)d_in[3];   // [64,16]
    const float* W_p    = (const float*)d_in[4];   // [1056,64]
    const float* b_p    = (const float*)d_in[5];   // [64]
    float* out = (float*)d_out;                    // [32,256,64,96]

    tpc_one<<<NBLK, 256>>>(x, statv, conv_w, conv_b, W_p, b_p, out);
}

// round 5
// speedup vs baseline: 1.3556x; 1.3556x over previous
#include <cuda_runtime.h>

#define B_   32
#define T_   256
#define F_   64
#define C_   16
#define CO_  16
#define P_   64
#define S_   32
#define K_   4
#define FC   1024
#define KIN  1056
#define OUTC 96
#define ROWS (B_*T_)        // 8192

// compact relu(point_out): 8192 x 64 fp32 = 2 MB (L2-resident)
__device__ __align__(256) float g_point[ROWS * P_];

// ---------------- packed f32x2 helpers ----------------
__device__ __forceinline__ double pack2(float lo, float hi) {
    double d; asm("mov.b64 %0, {%1, %2};" : "=d"(d) : "f"(lo), "f"(hi)); return d;
}
__device__ __forceinline__ float2 unpack2(double d) {
    float2 v; asm("mov.b64 {%0, %1}, %2;" : "=f"(v.x), "=f"(v.y) : "d"(d)); return v;
}
__device__ __forceinline__ void fma2(double& acc, double a, double b) {
    asm("fma.rn.f32x2 %0, %1, %2, %3;" : "=d"(acc) : "d"(a), "d"(b), "d"(acc));
}

// ============================================================================
// Kernel 1: point GEMM. grid=128, BM=64, BN=64, BK=32. 4m x 4n per thread.
// g_point[row, :] = relu(point_in[row, :] @ W_p + b_p)
// ============================================================================
__global__ __launch_bounds__(256, 2)
void tpc_gemm(const float* __restrict__ x,
              const float* __restrict__ stat,
              const float* __restrict__ W_p,
              const float* __restrict__ b_p)
{
    __shared__ __align__(16) float AsT[32][68];     // k-major A, 8.7 KB
    __shared__ __align__(16) float Bsdup[32][128];  // dup B, 16 KB

    const int tid  = threadIdx.x;
    const int row0 = blockIdx.x * 64;
    const int b    = row0 >> 8;
    const int mg   = tid >> 4;            // 0..15
    const int ng   = tid & 15;            // 0..15
    const int m0   = mg * 4;
    const int n0   = ng * 4;

    double acc[8];
    #pragma unroll
    for (int i = 0; i < 8; ++i) acc[i] = 0.0;

    for (int kb = 0; kb < 33; ++kb) {     // 33*32 = 1056
        const int kg0 = kb * 32;

        // A tile: 512 float4, 2 per thread, stored k-major
        #pragma unroll
        for (int l = 0; l < 2; ++l) {
            int idx = tid + l * 256;
            int r   = idx >> 3;           // 0..63
            int kq  = idx & 7;
            int kgf = kg0 + kq * 4;
            float4 v;
            if (kgf < FC)
                v = *reinterpret_cast<const float4*>(&x[(size_t)(row0 + r) * FC + kgf]);
            else
                v = *reinterpret_cast<const float4*>(&stat[b * S_ + (kgf - FC)]);
            AsT[kq * 4 + 0][r] = v.x;
            AsT[kq * 4 + 1][r] = v.y;
            AsT[kq * 4 + 2][r] = v.z;
            AsT[kq * 4 + 3][r] = v.w;
        }
        // B tile: 512 source float4, 2 per thread, duplicated
        #pragma unroll
        for (int l = 0; l < 2; ++l) {
            int idx = tid + l * 256;
            int kk  = idx >> 4;
            int nq  = idx & 15;
            float4 v = *reinterpret_cast<const float4*>(&W_p[(size_t)(kg0 + kk) * P_ + nq * 4]);
            *reinterpret_cast<float4*>(&Bsdup[kk][nq * 8])     = make_float4(v.x, v.x, v.y, v.y);
            *reinterpret_cast<float4*>(&Bsdup[kk][nq * 8 + 4]) = make_float4(v.z, v.z, v.w, v.w);
        }
        __syncthreads();

        #pragma unroll
        for (int kk = 0; kk < 32; ++kk) {
            double2 aa  = *reinterpret_cast<const double2*>(&AsT[kk][m0]);       // (m0,m0+1),(m0+2,m0+3)
            double2 b01 = *reinterpret_cast<const double2*>(&Bsdup[kk][n0 * 2]);
            double2 b23 = *reinterpret_cast<const double2*>(&Bsdup[kk][n0 * 2 + 4]);
            fma2(acc[0], aa.x, b01.x); fma2(acc[1], aa.x, b01.y);
            fma2(acc[2], aa.x, b23.x); fma2(acc[3], aa.x, b23.y);
            fma2(acc[4], aa.y, b01.x); fma2(acc[5], aa.y, b01.y);
            fma2(acc[6], aa.y, b23.x); fma2(acc[7], aa.y, b23.y);
        }
        __syncthreads();
    }

    float4 bb = *reinterpret_cast<const float4*>(&b_p[n0]);
    #pragma unroll
    for (int mp = 0; mp < 2; ++mp) {
        float2 p0 = unpack2(acc[mp * 4 + 0]);
        float2 p1 = unpack2(acc[mp * 4 + 1]);
        float2 p2 = unpack2(acc[mp * 4 + 2]);
        float2 p3 = unpack2(acc[mp * 4 + 3]);
        float4 lo = make_float4(fmaxf(p0.x + bb.x, 0.f), fmaxf(p1.x + bb.y, 0.f),
                                fmaxf(p2.x + bb.z, 0.f), fmaxf(p3.x + bb.w, 0.f));
        float4 hi = make_float4(fmaxf(p0.y + bb.x, 0.f), fmaxf(p1.y + bb.y, 0.f),
                                fmaxf(p2.y + bb.z, 0.f), fmaxf(p3.y + bb.w, 0.f));
        int row = row0 + m0 + 2 * mp;
        *reinterpret_cast<float4*>(&g_point[(size_t)row * P_ + n0])       = lo;
        *reinterpret_cast<float4*>(&g_point[(size_t)(row + 1) * P_ + n0]) = hi;
    }
}

// ============================================================================
// Kernel 2: conv per (b,f) + full 96-channel output assembly.
// grid = 2048, 256 threads. Thread micro-tile: 4 t x 4 co.
// ============================================================================
__global__ __launch_bounds__(256, 2)
void tpc_conv(const float* __restrict__ x,
              const float* __restrict__ conv_w,
              const float* __restrict__ conv_b,
              float* __restrict__ out)
{
    __shared__ __align__(16) double xsd[T_ + 6][17];  // dup-double x slab, 35.6 KB
    __shared__ __align__(16) float  ws[64][20];       // [c*4+k][co], 5.1 KB
    __shared__ __align__(16) float  stg[T_][20];      // conv results, 20.5 KB
    __shared__ __align__(16) float  bsv[16];

    const int tid = threadIdx.x;
    const int b   = blockIdx.x >> 6;
    const int f   = blockIdx.x & 63;
    const size_t xrow0 = (size_t)b * T_ * FC + (size_t)f * C_;   // x[b,0,f,0]

    // ---- x slab -> dup doubles (1048 float4 sources; rows 0..5 are zero pad) ----
    #pragma unroll
    for (int l = 0; l < 5; ++l) {
        int idx = tid + l * 256;
        if (idx < (T_ + 6) * 4) {
            int r = idx >> 2;             // 0..261, t = r - 6
            int q = idx & 3;
            float4 v = make_float4(0.f, 0.f, 0.f, 0.f);
            if (r >= 6)
                v = *reinterpret_cast<const float4*>(&x[xrow0 + (size_t)(r - 6) * FC + q * 4]);
            xsd[r][q * 4 + 0] = pack2(v.x, v.x);
            xsd[r][q * 4 + 1] = pack2(v.y, v.y);
            xsd[r][q * 4 + 2] = pack2(v.z, v.z);
            xsd[r][q * 4 + 3] = pack2(v.w, v.w);
        }
    }
    // ---- weights: 256 float4, transposed to [ck][co] ----
    {
        int co = tid >> 4;
        int c  = tid & 15;
        float4 w = *reinterpret_cast<const float4*>(&conv_w[((size_t)f * CO_ + co) * 64 + c * 4]);
        ws[c * 4 + 0][co] = w.x;
        ws[c * 4 + 1][co] = w.y;
        ws[c * 4 + 2][co] = w.z;
        ws[c * 4 + 3][co] = w.w;
    }
    if (tid < 16) bsv[tid] = conv_b[f * CO_ + tid];
    __syncthreads();

    // ---- conv: 4 t x 4 co per thread ----
    const int tg  = tid >> 2;             // 0..63
    const int cq  = tid & 3;              // 0..3
    const int t0  = tg * 4;
    const int co0 = cq * 4;

    double acc[4][2];                     // [t][co-pair]
    #pragma unroll
    for (int i = 0; i < 4; ++i) { acc[i][0] = 0.0; acc[i][1] = 0.0; }

    #pragma unroll 2
    for (int c = 0; c < C_; ++c) {
        double ad[10];
        #pragma unroll
        for (int r = 0; r < 10; ++r) ad[r] = xsd[t0 + r][c];
        #pragma unroll
        for (int k = 0; k < K_; ++k) {
            double2 w = *reinterpret_cast<const double2*>(&ws[c * 4 + k][co0]);
            #pragma unroll
            for (int i = 0; i < 4; ++i) {
                fma2(acc[i][0], ad[i + 2 * k], w.x);
                fma2(acc[i][1], ad[i + 2 * k], w.y);
            }
        }
    }
    // bias + relu -> staging
    {
        float4 bb = *reinterpret_cast<const float4*>(&bsv[co0]);
        #pragma unroll
        for (int i = 0; i < 4; ++i) {
            float2 q0 = unpack2(acc[i][0]);
            float2 q1 = unpack2(acc[i][1]);
            float4 v = make_float4(fmaxf(q0.x + bb.x, 0.f), fmaxf(q0.y + bb.y, 0.f),
                                   fmaxf(q1.x + bb.z, 0.f), fmaxf(q1.y + bb.w, 0.f));
            *reinterpret_cast<float4*>(&stg[t0 + i][co0]) = v;
        }
    }
    __syncthreads();

    // ---- output assembly: 3 uniform coalesced passes ----
    float* ob = out + ((size_t)b * T_ * F_ + f) * OUTC;          // + t*F_*OUTC + ch
    const float* gpb = g_point + (size_t)b * T_ * P_;

    // pass 1: ch 0..15 = relu(x), streamed from L2 (1024 float4)
    #pragma unroll
    for (int l = 0; l < 4; ++l) {
        int idx = tid + l * 256;
        int t   = idx >> 2;
        int q   = idx & 3;
        float4 v = *reinterpret_cast<const float4*>(&x[xrow0 + (size_t)t * FC + q * 4]);
        v.x = fmaxf(v.x, 0.f); v.y = fmaxf(v.y, 0.f);
        v.z = fmaxf(v.z, 0.f); v.w = fmaxf(v.w, 0.f);
        *reinterpret_cast<float4*>(&ob[(size_t)t * (F_ * OUTC) + q * 4]) = v;
    }
    // pass 2: ch 16..31 = conv results from smem (1024 float4)
    #pragma unroll
    for (int l = 0; l < 4; ++l) {
        int idx = tid + l * 256;
        int t   = idx >> 2;
        int q   = idx & 3;
        float4 v = *reinterpret_cast<const float4*>(&stg[t][q * 4]);
        *reinterpret_cast<float4*>(&ob[(size_t)t * (F_ * OUTC) + 16 + q * 4]) = v;
    }
    // pass 3: ch 32..95 = g_point broadcast from L2 (4096 float4)
    #pragma unroll
    for (int l = 0; l < 16; ++l) {
        int idx = tid + l * 256;
        int t   = idx >> 4;
        int q   = idx & 15;
        float4 v = *reinterpret_cast<const float4*>(&gpb[(size_t)t * P_ + q * 4]);
        *reinterpret_cast<float4*>(&ob[(size_t)t * (F_ * OUTC) + 32 + q * 4]) = v;
    }
}

extern "C" void kernel_launch(void* const* d_in, const int* in_sizes, int n_in,
                              void* d_out, int out_size)
{
    const float* x      = (const float*)d_in[0];   // [32,256,64,16]
    const float* statv  = (const float*)d_in[1];   // [32,32]
    const float* conv_w = (const float*)d_in[2];   // [64,16,16,4]
    const float* conv_b = (const float*)d_in[3];   // [64,16]
    const float* W_p    = (const float*)d_in[4];   // [1056,64]
    const float* b_p    = (const float*)d_in[5];   // [64]
    float* out = (float*)d_out;                    // [32,256,64,96]

    tpc_gemm<<<ROWS / 64, 256>>>(x, statv, W_p, b_p);
    tpc_conv<<<B_ * F_, 256>>>(x, conv_w, conv_b, out);
}